// round 10
// baseline (speedup 1.0000x reference)
#include <cuda_runtime.h>
#include <math.h>

#define NN 50000
#define EO 400000
#define EE 450000
#define F1 512
#define H1 8

// ---------------- scratch (device globals; no runtime allocation) ----------------
__device__ __align__(16) float g_xl1[(size_t)NN * F1];   // 102.4 MB
__device__ __align__(16) float g_xr1[(size_t)NN * F1];   // 102.4 MB
__device__ int   g_deg[NN];
__device__ int   g_rowptr[NN + 1];
__device__ int   g_cursor[NN];
__device__ int   g_eperm[EE];
__device__ float g_xl2[NN];
__device__ float g_xr2[NN];
__device__ float g_l2[EE];

__device__ __forceinline__ int srcof(const int* ei, int e) {
    return (e < EO) ? ei[e] : (e - EO);
}
__device__ __forceinline__ int dstof(const int* ei, int e) {
    return (e < EO) ? ei[EO + e] : (e - EO);
}
__device__ __forceinline__ float lrelu(float v) { return v > 0.0f ? v : 0.2f * v; }

// ---------------- K_init: zero degree histogram ----------------
__global__ void k_init0() {
    int t = blockIdx.x * blockDim.x + threadIdx.x;
    if (t < NN) g_deg[t] = 0;
}

// ---------------- K0: degree histogram ----------------
__global__ void k_degree(const int* __restrict__ ei) {
    int e = blockIdx.x * blockDim.x + threadIdx.x;
    if (e >= EE) return;
    atomicAdd(&g_deg[dstof(ei, e)], 1);
}

// ---------------- K1: thread-coarsened exclusive scan (rowptr + cursor) --------
__global__ void k_scan() {
    __shared__ int sh[1024];
    const int PER = (NN + 1023) / 1024;   // 49
    int t = threadIdx.x;
    int base = t * PER;
    int lim = (base < NN) ? min(PER, NN - base) : 0;
    int sum = 0;
    for (int k = 0; k < lim; k++) sum += g_deg[base + k];
    sh[t] = sum;
    __syncthreads();
    for (int off = 1; off < 1024; off <<= 1) {
        int add = (t >= off) ? sh[t - off] : 0;
        __syncthreads();
        sh[t] += add;
        __syncthreads();
    }
    int run = sh[t] - sum;                 // exclusive prefix of this segment
    for (int k = 0; k < lim; k++) {
        int v = g_deg[base + k];
        g_cursor[base + k] = run;
        run += v;
        g_rowptr[base + k + 1] = run;
    }
    if (t == 0) g_rowptr[0] = 0;
}

// ---------------- K2: scatter edge ids into CSR (dst-grouped) ----------------
__global__ void k_scatter(const int* __restrict__ ei) {
    int e = blockIdx.x * blockDim.x + threadIdx.x;
    if (e >= EE) return;
    int pos = atomicAdd(&g_cursor[dstof(ei, e)], 1);
    g_eperm[pos] = e;
}

// ---------------- K3: layer-1 linear transforms (64 nodes/block, W in regs) ----
#define GN 64
__global__ void __launch_bounds__(512) k_lin1(
    const float* __restrict__ x,
    const float* __restrict__ Wl, const float* __restrict__ bl,
    const float* __restrict__ Wr, const float* __restrict__ br) {
    __shared__ float xs[GN][24];
    int t = threadIdx.x;
    int n0 = blockIdx.x * GN;
    for (int idx = t; idx < GN * 23; idx += 512) {
        int n = idx / 23, k = idx % 23;
        int gi = n0 + n;
        xs[n][k] = (gi < NN) ? x[gi * 23 + k] : 0.0f;
    }
    float wl[23], wr[23];
#pragma unroll
    for (int k = 0; k < 23; k++) { wl[k] = Wl[k * F1 + t]; wr[k] = Wr[k * F1 + t]; }
    float bll = bl[t], brr = br[t];
    __syncthreads();
    for (int n = 0; n < GN; n++) {
        int gi = n0 + n;
        if (gi >= NN) break;
        float al = bll, ar = brr;
#pragma unroll
        for (int k = 0; k < 23; k++) {
            float xv = xs[n][k];
            al = fmaf(xv, wl[k], al);
            ar = fmaf(xv, wr[k], ar);
        }
        g_xl1[(size_t)gi * F1 + t] = al;
        g_xr1[(size_t)gi * F1 + t] = ar;
    }
}

// ---------------- K4: fused layer-1 attention (block = dst node, 256 thr) ------
// Single-read design: each warp gathers its edges' rows into registers, computes
// the 8 head logits (xor-reduce), and folds the row straight into per-warp
// online-softmax accumulators. Warps merge via split-softmax in smem.
// Epilogue: bias+relu, fused layer-2 input projections -> g_xl2/g_xr2.
#define BT 256
__global__ void __launch_bounds__(BT) k_fused1(
    const int* __restrict__ ei,
    const float* __restrict__ att,
    const float* __restrict__ bias1,
    const float* __restrict__ Wl2, const float* __restrict__ bl2,
    const float* __restrict__ Wr2, const float* __restrict__ br2) {
    __shared__ float s_xr[F1];                 // 2 KB
    __shared__ float s_att[F1];                // 2 KB
    __shared__ __align__(16) float s_acc[8][F1];  // 16 KB: per-warp partial rows
    __shared__ float s_m[8][H1];               // per-warp per-head max -> scale
    __shared__ float s_den[8][H1];
    __shared__ float s_dtot[H1];
    __shared__ float s_r1[8], s_r2[8];

    int i = blockIdx.x;
    int t = threadIdx.x;
    int w = t >> 5, lane = t & 31;
    int start = g_rowptr[i], end = g_rowptr[i + 1];

    s_xr[t]        = g_xr1[(size_t)i * F1 + t];
    s_xr[t + 256]  = g_xr1[(size_t)i * F1 + t + 256];
    s_att[t]       = att[t];
    s_att[t + 256] = att[t + 256];
    __syncthreads();

    // per-warp online-softmax state; block k covers heads {2k,2k+1}
    // (lane<16 -> 2k, lane>=16 -> 2k+1); each lane's features: 128k+4*lane..+3
    float  m[4]   = {-INFINITY, -INFINITY, -INFINITY, -INFINITY};
    float  den[4] = {0.0f, 0.0f, 0.0f, 0.0f};
    float4 acc[4];
#pragma unroll
    for (int k = 0; k < 4; k++) acc[k] = make_float4(0.f, 0.f, 0.f, 0.f);

    for (int j = start + w; j < end; j += 8) {
        int e = g_eperm[j];
        int s = srcof(ei, e);
        const float4* prow = (const float4*)(g_xl1 + (size_t)s * F1);
        float4 v[4];
        float  p[4];
#pragma unroll
        for (int k = 0; k < 4; k++) {
            int fi = k * 32 + lane;
            v[k] = prow[fi];
            float4 x4 = ((const float4*)s_xr)[fi];
            float4 a4 = ((const float4*)s_att)[fi];
            p[k] = fmaf(lrelu(v[k].x + x4.x), a4.x,
                   fmaf(lrelu(v[k].y + x4.y), a4.y,
                   fmaf(lrelu(v[k].z + x4.z), a4.z,
                        lrelu(v[k].w + x4.w) * a4.w)));
        }
#pragma unroll
        for (int off = 1; off < 16; off <<= 1) {
#pragma unroll
            for (int k = 0; k < 4; k++)
                p[k] += __shfl_xor_sync(0xffffffffu, p[k], off);
        }
        // online update: p[k] is this edge's logit for lane's head in block k
#pragma unroll
        for (int k = 0; k < 4; k++) {
            float nm  = fmaxf(m[k], p[k]);
            float sc  = expf(m[k] - nm);       // 1 if unchanged; 0 on first edge
            float wgt = expf(p[k] - nm);
            den[k] = den[k] * sc + wgt;
            acc[k].x = fmaf(acc[k].x, sc, wgt * v[k].x);
            acc[k].y = fmaf(acc[k].y, sc, wgt * v[k].y);
            acc[k].z = fmaf(acc[k].z, sc, wgt * v[k].z);
            acc[k].w = fmaf(acc[k].w, sc, wgt * v[k].w);
            m[k] = nm;
        }
    }

    // publish per-warp state
    if (lane == 0) {
#pragma unroll
        for (int k = 0; k < 4; k++) { s_m[w][2 * k] = m[k]; s_den[w][2 * k] = den[k]; }
    }
    if (lane == 16) {
#pragma unroll
        for (int k = 0; k < 4; k++) { s_m[w][2 * k + 1] = m[k]; s_den[w][2 * k + 1] = den[k]; }
    }
#pragma unroll
    for (int k = 0; k < 4; k++)
        ((float4*)s_acc[w])[k * 32 + lane] = acc[k];
    __syncthreads();

    // split-softmax merge: thread h (<8) computes global max + total denom,
    // rewrites s_m[w][h] as that warp's rescale factor
    if (t < H1) {
        float M = -INFINITY;
#pragma unroll
        for (int ww = 0; ww < 8; ww++) M = fmaxf(M, s_m[ww][t]);
        float dtot = 0.0f;
#pragma unroll
        for (int ww = 0; ww < 8; ww++) {
            float sc = expf(s_m[ww][t] - M);   // 0 for edgeless warps
            s_m[ww][t] = sc;
            dtot = fmaf(sc, s_den[ww][t], dtot);
        }
        s_dtot[t] = dtot;
    }
    __syncthreads();

    // reduce partial rows: thread t handles features t and t+256
    int hA = t >> 6, hB = hA + 4;
    float a0 = 0.0f, a1 = 0.0f;
#pragma unroll
    for (int ww = 0; ww < 8; ww++) {
        a0 = fmaf(s_m[ww][hA], s_acc[ww][t],       a0);
        a1 = fmaf(s_m[ww][hB], s_acc[ww][t + 256], a1);
    }
    float r0 = fmaxf(a0 / s_dtot[hA] + bias1[t],       0.0f);
    float r1 = fmaxf(a1 / s_dtot[hB] + bias1[t + 256], 0.0f);

    // fused layer-2 projections + block reduce
    float pl = fmaf(r0, Wl2[t], r1 * Wl2[t + 256]);
    float pr = fmaf(r0, Wr2[t], r1 * Wr2[t + 256]);
#pragma unroll
    for (int off = 16; off > 0; off >>= 1) {
        pl += __shfl_down_sync(0xffffffffu, pl, off);
        pr += __shfl_down_sync(0xffffffffu, pr, off);
    }
    if (lane == 0) { s_r1[w] = pl; s_r2[w] = pr; }
    __syncthreads();
    if (t < 8) {
        pl = s_r1[t]; pr = s_r2[t];
#pragma unroll
        for (int off = 4; off > 0; off >>= 1) {
            pl += __shfl_down_sync(0x000000ffu, pl, off);
            pr += __shfl_down_sync(0x000000ffu, pr, off);
        }
        if (t == 0) {
            g_xl2[i] = pl + bl2[0];
            g_xr2[i] = pr + br2[0];
        }
    }
}

// ---------------- K5: fused layer-2 (warp = dst node) --------------------------
// Logits stored at CSR position j (coalesced) so pass 2 needs no eperm gather.
__global__ void k_l2(const int* __restrict__ ei,
                     const float* __restrict__ att2,
                     const float* __restrict__ bias2,
                     float* __restrict__ out) {
    int gw = (blockIdx.x * blockDim.x + threadIdx.x) >> 5;
    if (gw >= NN) return;
    int lane = threadIdx.x & 31;
    int i = gw;
    int start = g_rowptr[i], end = g_rowptr[i + 1];
    float a2 = att2[0];
    float xr = g_xr2[i];

    // pass 1: logits + warp max
    float m = -INFINITY;
    for (int j = start + lane; j < end; j += 32) {
        int e = g_eperm[j];
        float l = lrelu(g_xl2[srcof(ei, e)] + xr) * a2;
        g_l2[j] = l;
        m = fmaxf(m, l);
    }
#pragma unroll
    for (int off = 16; off > 0; off >>= 1)
        m = fmaxf(m, __shfl_xor_sync(0xffffffffu, m, off));

    // pass 2: denominator (coalesced)
    float den = 0.0f;
    for (int j = start + lane; j < end; j += 32)
        den += expf(g_l2[j] - m);
#pragma unroll
    for (int off = 16; off > 0; off >>= 1)
        den += __shfl_xor_sync(0xffffffffu, den, off);
    float invden = 1.0f / den;

    // pass 3: alpha out + weighted sum
    float acc = 0.0f;
    for (int j = start + lane; j < end; j += 32) {
        int e = g_eperm[j];
        float alpha = expf(g_l2[j] - m) * invden;
        out[NN + e] = alpha;
        acc = fmaf(alpha, g_xl2[srcof(ei, e)], acc);
    }
#pragma unroll
    for (int off = 16; off > 0; off >>= 1)
        acc += __shfl_xor_sync(0xffffffffu, acc, off);
    if (lane == 0) out[i] = acc + bias2[0];
}

// ---------------- launch ----------------
extern "C" void kernel_launch(void* const* d_in, const int* in_sizes, int n_in,
                              void* d_out, int out_size) {
    const float* x     = (const float*)d_in[0];
    const int*   ei    = (const int*)d_in[1];
    const float* Wl1   = (const float*)d_in[2];
    const float* bl1   = (const float*)d_in[3];
    const float* Wr1   = (const float*)d_in[4];
    const float* br1   = (const float*)d_in[5];
    const float* att1  = (const float*)d_in[6];
    const float* bias1 = (const float*)d_in[7];
    const float* Wl2   = (const float*)d_in[8];
    const float* bl2   = (const float*)d_in[9];
    const float* Wr2   = (const float*)d_in[10];
    const float* br2   = (const float*)d_in[11];
    const float* att2  = (const float*)d_in[12];
    const float* bias2 = (const float*)d_in[13];
    float* out = (float*)d_out;

    k_init0 <<<(NN + 255) / 256, 256>>>();
    k_degree<<<(EE + 255) / 256, 256>>>(ei);
    k_scan  <<<1, 1024>>>();
    k_scatter<<<(EE + 255) / 256, 256>>>(ei);
    k_lin1  <<<(NN + GN - 1) / GN, 512>>>(x, Wl1, bl1, Wr1, br1);
    k_fused1<<<NN, BT>>>(ei, att1, bias1, Wl2, bl2, Wr2, br2);
    k_l2    <<<(NN * 32 + 255) / 256, 256>>>(ei, att2, bias2, out);
}

// round 12
// speedup vs baseline: 1.6871x; 1.6871x over previous
#include <cuda_runtime.h>
#include <math.h>

#define NN 50000
#define EO 400000
#define EE 450000
#define F1 512
#define H1 8

// ---------------- scratch (device globals; no runtime allocation) ----------------
__device__ __align__(16) float g_xl1[(size_t)NN * F1];   // 102.4 MB
__device__ __align__(16) float g_xr1[(size_t)NN * F1];   // 102.4 MB
__device__ int   g_deg[NN];
__device__ int   g_rowptr[NN + 1];
__device__ int   g_cursor[NN];
__device__ int   g_eperm[EE];
__device__ float g_xl2[NN];
__device__ float g_xr2[NN];
__device__ float g_l2[EE];

__device__ __forceinline__ int srcof(const int* ei, int e) {
    return (e < EO) ? ei[e] : (e - EO);
}
__device__ __forceinline__ int dstof(const int* ei, int e) {
    return (e < EO) ? ei[EO + e] : (e - EO);
}
__device__ __forceinline__ float lrelu(float v) { return v > 0.0f ? v : 0.2f * v; }

// ---------------- K_init: zero degree histogram ----------------
__global__ void k_init0() {
    int t = blockIdx.x * blockDim.x + threadIdx.x;
    if (t < NN) g_deg[t] = 0;
}

// ---------------- K0: degree histogram ----------------
__global__ void k_degree(const int* __restrict__ ei) {
    int e = blockIdx.x * blockDim.x + threadIdx.x;
    if (e >= EE) return;
    atomicAdd(&g_deg[dstof(ei, e)], 1);
}

// ---------------- K1: thread-coarsened exclusive scan (rowptr + cursor) --------
__global__ void k_scan() {
    __shared__ int sh[1024];
    const int PER = (NN + 1023) / 1024;   // 49
    int t = threadIdx.x;
    int base = t * PER;
    int lim = (base < NN) ? min(PER, NN - base) : 0;
    int sum = 0;
    for (int k = 0; k < lim; k++) sum += g_deg[base + k];
    sh[t] = sum;
    __syncthreads();
    for (int off = 1; off < 1024; off <<= 1) {
        int add = (t >= off) ? sh[t - off] : 0;
        __syncthreads();
        sh[t] += add;
        __syncthreads();
    }
    int run = sh[t] - sum;                 // exclusive prefix of this segment
    for (int k = 0; k < lim; k++) {
        int v = g_deg[base + k];
        g_cursor[base + k] = run;
        run += v;
        g_rowptr[base + k + 1] = run;
    }
    if (t == 0) g_rowptr[0] = 0;
}

// ---------------- K2: scatter edge ids into CSR (dst-grouped) ----------------
__global__ void k_scatter(const int* __restrict__ ei) {
    int e = blockIdx.x * blockDim.x + threadIdx.x;
    if (e >= EE) return;
    int pos = atomicAdd(&g_cursor[dstof(ei, e)], 1);
    g_eperm[pos] = e;
}

// ---------------- K3: layer-1 linear transforms (64 nodes/block, W in regs) ----
#define GN 64
__global__ void __launch_bounds__(512) k_lin1(
    const float* __restrict__ x,
    const float* __restrict__ Wl, const float* __restrict__ bl,
    const float* __restrict__ Wr, const float* __restrict__ br) {
    __shared__ float xs[GN][24];
    int t = threadIdx.x;
    int n0 = blockIdx.x * GN;
    for (int idx = t; idx < GN * 23; idx += 512) {
        int n = idx / 23, k = idx % 23;
        int gi = n0 + n;
        xs[n][k] = (gi < NN) ? x[gi * 23 + k] : 0.0f;
    }
    float wl[23], wr[23];
#pragma unroll
    for (int k = 0; k < 23; k++) { wl[k] = Wl[k * F1 + t]; wr[k] = Wr[k * F1 + t]; }
    float bll = bl[t], brr = br[t];
    __syncthreads();
    for (int n = 0; n < GN; n++) {
        int gi = n0 + n;
        if (gi >= NN) break;
        float al = bll, ar = brr;
#pragma unroll
        for (int k = 0; k < 23; k++) {
            float xv = xs[n][k];
            al = fmaf(xv, wl[k], al);
            ar = fmaf(xv, wr[k], ar);
        }
        g_xl1[(size_t)gi * F1 + t] = al;
        g_xr1[(size_t)gi * F1 + t] = ar;
    }
}

// ---------------- K4: fused layer-1 attention (block = dst node, 128 thr) ------
// Thread t owns float4 feature slot t (features 4t..4t+3, head t>>4).
// Phase 1: warp-per-edge logits. Phase 2: warp w -> heads {w, w+4}, online
// softmax. Phase 3: coalesced float4 re-gather (L1/L2-hot) + accumulate.
// Epilogue: bias+relu, fused layer-2 input projections -> g_xl2/g_xr2.
#define BT 128
#define CHF 32
__global__ void __launch_bounds__(BT) k_fused1(
    const int* __restrict__ ei,
    const float* __restrict__ att,
    const float* __restrict__ bias1,
    const float* __restrict__ Wl2, const float* __restrict__ bl2,
    const float* __restrict__ Wr2, const float* __restrict__ br2) {
    __shared__ __align__(16) float s_xr[F1];   // 2 KB
    __shared__ __align__(16) float s_att[F1];  // 2 KB
    __shared__ float s_lg[CHF][9];             // logits -> weights (padded)
    __shared__ int   s_src[CHF];
    __shared__ float s_m[H1], s_den[H1], s_scale[H1];
    __shared__ float s_r1[4], s_r2[4];

    int i = blockIdx.x;
    int t = threadIdx.x;
    int w = t >> 5, lane = t & 31;
    int start = g_rowptr[i], end = g_rowptr[i + 1];

    {   // load xr row (streaming: read-once) + att
        const float4* xr4 = (const float4*)(g_xr1 + (size_t)i * F1);
        ((float4*)s_xr)[t] = __ldcs(&xr4[t]);
        s_att[t]       = att[t];
        s_att[t + 128] = att[t + 128];
        s_att[t + 256] = att[t + 256];
        s_att[t + 384] = att[t + 384];
    }
    if (t < H1) { s_m[t] = -INFINITY; s_den[t] = 0.0f; }
    __syncthreads();

    int h4 = t >> 4;                           // head of this thread's float4 slot
    float4 acc = make_float4(0.f, 0.f, 0.f, 0.f);

    for (int c = start; c < end; c += CHF) {
        int m_e = min(CHF, end - c);

        // ---- phase 1: logits, warp per edge (strided by 4 warps) ----
        for (int le = w; le < m_e; le += 4) {
            int e = g_eperm[c + le];
            int s = srcof(ei, e);
            if (lane == 0) s_src[le] = s;
            const float4* prow = (const float4*)(g_xl1 + (size_t)s * F1);
            float p[4];
#pragma unroll
            for (int k = 0; k < 4; k++) {
                int fi = k * 32 + lane;
                float4 v  = prow[fi];
                float4 x4 = ((const float4*)s_xr)[fi];
                float4 a4 = ((const float4*)s_att)[fi];
                p[k] = fmaf(lrelu(v.x + x4.x), a4.x,
                       fmaf(lrelu(v.y + x4.y), a4.y,
                       fmaf(lrelu(v.z + x4.z), a4.z,
                            lrelu(v.w + x4.w) * a4.w)));
            }
            // block k covers heads {2k, 2k+1}: lanes<16 -> 2k, lanes>=16 -> 2k+1
#pragma unroll
            for (int off = 1; off < 16; off <<= 1) {
#pragma unroll
                for (int k = 0; k < 4; k++)
                    p[k] += __shfl_xor_sync(0xffffffffu, p[k], off);
            }
            if (lane == 0)  { s_lg[le][0] = p[0]; s_lg[le][2] = p[1]; s_lg[le][4] = p[2]; s_lg[le][6] = p[3]; }
            if (lane == 16) { s_lg[le][1] = p[0]; s_lg[le][3] = p[1]; s_lg[le][5] = p[2]; s_lg[le][7] = p[3]; }
        }
        __syncthreads();

        // ---- phase 2: online softmax, warp w handles heads w and w+4 ----
        for (int hh = w; hh < H1; hh += 4) {
            float cm = -INFINITY;
            for (int j = lane; j < m_e; j += 32) cm = fmaxf(cm, s_lg[j][hh]);
#pragma unroll
            for (int off = 16; off > 0; off >>= 1)
                cm = fmaxf(cm, __shfl_xor_sync(0xffffffffu, cm, off));
            float m_old = s_m[hh];
            cm = fmaxf(cm, m_old);
            float dn = 0.0f;
            for (int j = lane; j < m_e; j += 32) {
                float wj = expf(s_lg[j][hh] - cm);
                s_lg[j][hh] = wj;
                dn += wj;
            }
#pragma unroll
            for (int off = 16; off > 0; off >>= 1)
                dn += __shfl_xor_sync(0xffffffffu, dn, off);
            if (lane == 0) {
                float sc = expf(m_old - cm);    // first chunk: exp(-inf)=0
                s_scale[hh] = sc;
                s_den[hh] = s_den[hh] * sc + dn;
                s_m[hh] = cm;
            }
        }
        __syncthreads();

        // ---- phase 3: coalesced float4 aggregation (rows L1/L2-hot) ----
        {
            float scl = s_scale[h4];
            acc.x *= scl; acc.y *= scl; acc.z *= scl; acc.w *= scl;
        }
        for (int j = 0; j < m_e; j++) {
            const float4* row = (const float4*)(g_xl1 + (size_t)s_src[j] * F1);
            float4 v = row[t];
            float wg = s_lg[j][h4];
            acc.x = fmaf(wg, v.x, acc.x);
            acc.y = fmaf(wg, v.y, acc.y);
            acc.z = fmaf(wg, v.z, acc.z);
            acc.w = fmaf(wg, v.w, acc.w);
        }
        __syncthreads();                       // protect s_lg/s_src reuse
    }

    // epilogue: normalize, bias, relu; fused layer-2 projections + block reduce
    float invd = 1.0f / s_den[h4];
    int f0 = 4 * t;
    float r0 = fmaxf(fmaf(acc.x, invd, bias1[f0 + 0]), 0.0f);
    float r1 = fmaxf(fmaf(acc.y, invd, bias1[f0 + 1]), 0.0f);
    float r2 = fmaxf(fmaf(acc.z, invd, bias1[f0 + 2]), 0.0f);
    float r3 = fmaxf(fmaf(acc.w, invd, bias1[f0 + 3]), 0.0f);
    float pl = fmaf(r0, Wl2[f0], fmaf(r1, Wl2[f0 + 1],
               fmaf(r2, Wl2[f0 + 2], r3 * Wl2[f0 + 3])));
    float pr = fmaf(r0, Wr2[f0], fmaf(r1, Wr2[f0 + 1],
               fmaf(r2, Wr2[f0 + 2], r3 * Wr2[f0 + 3])));
#pragma unroll
    for (int off = 16; off > 0; off >>= 1) {
        pl += __shfl_down_sync(0xffffffffu, pl, off);
        pr += __shfl_down_sync(0xffffffffu, pr, off);
    }
    if (lane == 0) { s_r1[w] = pl; s_r2[w] = pr; }
    __syncthreads();
    if (t == 0) {
        g_xl2[i] = s_r1[0] + s_r1[1] + s_r1[2] + s_r1[3] + bl2[0];
        g_xr2[i] = s_r2[0] + s_r2[1] + s_r2[2] + s_r2[3] + br2[0];
    }
}

// ---------------- K5: fused layer-2 (warp = dst node) --------------------------
// Logits stored at CSR position j (coalesced) so pass 2 needs no eperm gather.
__global__ void k_l2(const int* __restrict__ ei,
                     const float* __restrict__ att2,
                     const float* __restrict__ bias2,
                     float* __restrict__ out) {
    int gw = (blockIdx.x * blockDim.x + threadIdx.x) >> 5;
    if (gw >= NN) return;
    int lane = threadIdx.x & 31;
    int i = gw;
    int start = g_rowptr[i], end = g_rowptr[i + 1];
    float a2 = att2[0];
    float xr = g_xr2[i];

    // pass 1: logits + warp max
    float m = -INFINITY;
    for (int j = start + lane; j < end; j += 32) {
        int e = g_eperm[j];
        float l = lrelu(g_xl2[srcof(ei, e)] + xr) * a2;
        g_l2[j] = l;
        m = fmaxf(m, l);
    }
#pragma unroll
    for (int off = 16; off > 0; off >>= 1)
        m = fmaxf(m, __shfl_xor_sync(0xffffffffu, m, off));

    // pass 2: denominator (coalesced)
    float den = 0.0f;
    for (int j = start + lane; j < end; j += 32)
        den += expf(g_l2[j] - m);
#pragma unroll
    for (int off = 16; off > 0; off >>= 1)
        den += __shfl_xor_sync(0xffffffffu, den, off);
    float invden = 1.0f / den;

    // pass 3: alpha out + weighted sum
    float acc = 0.0f;
    for (int j = start + lane; j < end; j += 32) {
        int e = g_eperm[j];
        float alpha = expf(g_l2[j] - m) * invden;
        out[NN + e] = alpha;
        acc = fmaf(alpha, g_xl2[srcof(ei, e)], acc);
    }
#pragma unroll
    for (int off = 16; off > 0; off >>= 1)
        acc += __shfl_xor_sync(0xffffffffu, acc, off);
    if (lane == 0) out[i] = acc + bias2[0];
}

// ---------------- launch ----------------
extern "C" void kernel_launch(void* const* d_in, const int* in_sizes, int n_in,
                              void* d_out, int out_size) {
    const float* x     = (const float*)d_in[0];
    const int*   ei    = (const int*)d_in[1];
    const float* Wl1   = (const float*)d_in[2];
    const float* bl1   = (const float*)d_in[3];
    const float* Wr1   = (const float*)d_in[4];
    const float* br1   = (const float*)d_in[5];
    const float* att1  = (const float*)d_in[6];
    const float* bias1 = (const float*)d_in[7];
    const float* Wl2   = (const float*)d_in[8];
    const float* bl2   = (const float*)d_in[9];
    const float* Wr2   = (const float*)d_in[10];
    const float* br2   = (const float*)d_in[11];
    const float* att2  = (const float*)d_in[12];
    const float* bias2 = (const float*)d_in[13];
    float* out = (float*)d_out;

    k_init0 <<<(NN + 255) / 256, 256>>>();
    k_degree<<<(EE + 255) / 256, 256>>>(ei);
    k_scan  <<<1, 1024>>>();
    k_scatter<<<(EE + 255) / 256, 256>>>(ei);
    k_lin1  <<<(NN + GN - 1) / GN, 512>>>(x, Wl1, bl1, Wr1, br1);
    k_fused1<<<NN, BT>>>(ei, att1, bias1, Wl2, bl2, Wr2, br2);
    k_l2    <<<(NN * 32 + 255) / 256, 256>>>(ei, att2, bias2, out);
}

// round 14
// speedup vs baseline: 1.7904x; 1.0612x over previous
#include <cuda_runtime.h>
#include <math.h>

#define NN 50000
#define EO 400000
#define EE 450000
#define F1 512
#define H1 8

// ---------------- scratch (device globals; no runtime allocation) ----------------
__device__ __align__(16) float g_xl1[(size_t)NN * F1];   // 102.4 MB
__device__ __align__(16) float g_xr1[(size_t)NN * F1];   // 102.4 MB
__device__ int   g_deg[NN];
__device__ int   g_rowptr[NN + 1];
__device__ int   g_cursor[NN];
__device__ int   g_eperm[EE];      // edge id in CSR(dst) order
__device__ int   g_esrc[EE];       // src node in CSR(dst) order
__device__ float g_xl2[NN];
__device__ float g_xr2[NN];
__device__ float g_l2[EE];

__device__ __forceinline__ int srcof(const int* ei, int e) {
    return (e < EO) ? ei[e] : (e - EO);
}
__device__ __forceinline__ int dstof(const int* ei, int e) {
    return (e < EO) ? ei[EO + e] : (e - EO);
}
__device__ __forceinline__ float lrelu(float v) { return v > 0.0f ? v : 0.2f * v; }

// ---------------- K_init: zero degree histogram ----------------
__global__ void k_init0() {
    int t = blockIdx.x * blockDim.x + threadIdx.x;
    if (t < NN) g_deg[t] = 0;
}

// ---------------- K0: degree histogram ----------------
__global__ void k_degree(const int* __restrict__ ei) {
    int e = blockIdx.x * blockDim.x + threadIdx.x;
    if (e >= EE) return;
    atomicAdd(&g_deg[dstof(ei, e)], 1);
}

// ---------------- K1: thread-coarsened exclusive scan (rowptr + cursor) --------
__global__ void k_scan() {
    __shared__ int sh[1024];
    const int PER = (NN + 1023) / 1024;   // 49
    int t = threadIdx.x;
    int base = t * PER;
    int lim = (base < NN) ? min(PER, NN - base) : 0;
    int sum = 0;
    for (int k = 0; k < lim; k++) sum += g_deg[base + k];
    sh[t] = sum;
    __syncthreads();
    for (int off = 1; off < 1024; off <<= 1) {
        int add = (t >= off) ? sh[t - off] : 0;
        __syncthreads();
        sh[t] += add;
        __syncthreads();
    }
    int run = sh[t] - sum;                 // exclusive prefix of this segment
    for (int k = 0; k < lim; k++) {
        int v = g_deg[base + k];
        g_cursor[base + k] = run;
        run += v;
        g_rowptr[base + k + 1] = run;
    }
    if (t == 0) g_rowptr[0] = 0;
}

// ---------------- K2: scatter edge ids + src into CSR (dst-grouped) ----------
__global__ void k_scatter(const int* __restrict__ ei) {
    int e = blockIdx.x * blockDim.x + threadIdx.x;
    if (e >= EE) return;
    int s, d;
    if (e < EO) { s = ei[e]; d = ei[EO + e]; }
    else        { s = e - EO; d = s; }
    int pos = atomicAdd(&g_cursor[d], 1);
    g_eperm[pos] = e;
    g_esrc[pos]  = s;
}

// ---------------- K3: layer-1 linear transforms (64 nodes/block, W in regs) ----
#define GN 64
__global__ void __launch_bounds__(512) k_lin1(
    const float* __restrict__ x,
    const float* __restrict__ Wl, const float* __restrict__ bl,
    const float* __restrict__ Wr, const float* __restrict__ br) {
    __shared__ float xs[GN][24];
    int t = threadIdx.x;
    int n0 = blockIdx.x * GN;
    for (int idx = t; idx < GN * 23; idx += 512) {
        int n = idx / 23, k = idx % 23;
        int gi = n0 + n;
        xs[n][k] = (gi < NN) ? x[gi * 23 + k] : 0.0f;
    }
    float wl[23], wr[23];
#pragma unroll
    for (int k = 0; k < 23; k++) { wl[k] = Wl[k * F1 + t]; wr[k] = Wr[k * F1 + t]; }
    float bll = bl[t], brr = br[t];
    __syncthreads();
    for (int n = 0; n < GN; n++) {
        int gi = n0 + n;
        if (gi >= NN) break;
        float al = bll, ar = brr;
#pragma unroll
        for (int k = 0; k < 23; k++) {
            float xv = xs[n][k];
            al = fmaf(xv, wl[k], al);
            ar = fmaf(xv, wr[k], ar);
        }
        g_xl1[(size_t)gi * F1 + t] = al;
        g_xr1[(size_t)gi * F1 + t] = ar;
    }
}

// ---------------- K4: fused layer-1 attention (block = dst node, 128 thr) ------
// Thread t owns float4 feature slot t (features 4t..4t+3, head t>>4).
// Phase 1: warp-per-edge logits, src read straight from g_esrc (1-level chain)
// with next-src prefetch. Phase 2: warp w -> heads {w, w+4}, online softmax.
// Phase 3: coalesced float4 re-gather (L1-hot) + accumulate.
// Epilogue: bias+relu, fused layer-2 input projections -> g_xl2/g_xr2.
#define BT 128
#define CHF 32
__global__ void __launch_bounds__(BT) k_fused1(
    const float* __restrict__ att,
    const float* __restrict__ bias1,
    const float* __restrict__ Wl2, const float* __restrict__ bl2,
    const float* __restrict__ Wr2, const float* __restrict__ br2) {
    __shared__ __align__(16) float s_xr[F1];   // 2 KB
    __shared__ __align__(16) float s_att[F1];  // 2 KB
    __shared__ float s_lg[CHF][9];             // logits -> weights (padded)
    __shared__ int   s_src[CHF];
    __shared__ float s_m[H1], s_den[H1], s_scale[H1];
    __shared__ float s_r1[4], s_r2[4];

    int i = blockIdx.x;
    int t = threadIdx.x;
    int w = t >> 5, lane = t & 31;
    int start = g_rowptr[i], end = g_rowptr[i + 1];

    {   // load xr row (streaming: read-once) + att
        const float4* xr4 = (const float4*)(g_xr1 + (size_t)i * F1);
        ((float4*)s_xr)[t] = __ldcs(&xr4[t]);
        s_att[t]       = att[t];
        s_att[t + 128] = att[t + 128];
        s_att[t + 256] = att[t + 256];
        s_att[t + 384] = att[t + 384];
    }
    if (t < H1) { s_m[t] = -INFINITY; s_den[t] = 0.0f; }
    __syncthreads();

    int h4 = t >> 4;                           // head of this thread's float4 slot
    float4 acc = make_float4(0.f, 0.f, 0.f, 0.f);

    for (int c = start; c < end; c += CHF) {
        int m_e = min(CHF, end - c);

        // ---- phase 1: logits, warp per edge (strided by 4 warps), pipelined ----
        {
            int le = w;
            int s_cur = (le < m_e) ? g_esrc[c + le] : 0;
            for (; le < m_e; le += 4) {
                int s_nxt = (le + 4 < m_e) ? g_esrc[c + le + 4] : 0;
                if (lane == 0) s_src[le] = s_cur;
                const float4* prow = (const float4*)(g_xl1 + (size_t)s_cur * F1);
                float p[4];
#pragma unroll
                for (int k = 0; k < 4; k++) {
                    int fi = k * 32 + lane;
                    float4 v  = prow[fi];
                    float4 x4 = ((const float4*)s_xr)[fi];
                    float4 a4 = ((const float4*)s_att)[fi];
                    p[k] = fmaf(lrelu(v.x + x4.x), a4.x,
                           fmaf(lrelu(v.y + x4.y), a4.y,
                           fmaf(lrelu(v.z + x4.z), a4.z,
                                lrelu(v.w + x4.w) * a4.w)));
                }
                // block k covers heads {2k,2k+1}: lanes<16 -> 2k, lanes>=16 -> 2k+1
#pragma unroll
                for (int off = 1; off < 16; off <<= 1) {
#pragma unroll
                    for (int k = 0; k < 4; k++)
                        p[k] += __shfl_xor_sync(0xffffffffu, p[k], off);
                }
                if (lane == 0)  { s_lg[le][0] = p[0]; s_lg[le][2] = p[1]; s_lg[le][4] = p[2]; s_lg[le][6] = p[3]; }
                if (lane == 16) { s_lg[le][1] = p[0]; s_lg[le][3] = p[1]; s_lg[le][5] = p[2]; s_lg[le][7] = p[3]; }
                s_cur = s_nxt;
            }
        }
        __syncthreads();

        // ---- phase 2: online softmax, warp w handles heads w and w+4 ----
        for (int hh = w; hh < H1; hh += 4) {
            float cm = -INFINITY;
            for (int j = lane; j < m_e; j += 32) cm = fmaxf(cm, s_lg[j][hh]);
#pragma unroll
            for (int off = 16; off > 0; off >>= 1)
                cm = fmaxf(cm, __shfl_xor_sync(0xffffffffu, cm, off));
            float m_old = s_m[hh];
            cm = fmaxf(cm, m_old);
            float dn = 0.0f;
            for (int j = lane; j < m_e; j += 32) {
                float wj = __expf(s_lg[j][hh] - cm);
                s_lg[j][hh] = wj;
                dn += wj;
            }
#pragma unroll
            for (int off = 16; off > 0; off >>= 1)
                dn += __shfl_xor_sync(0xffffffffu, dn, off);
            if (lane == 0) {
                float sc = __expf(m_old - cm);  // first chunk: exp(-inf)=0
                s_scale[hh] = sc;
                s_den[hh] = s_den[hh] * sc + dn;
                s_m[hh] = cm;
            }
        }
        __syncthreads();

        // ---- phase 3: coalesced float4 aggregation (rows L1-hot) ----
        {
            float scl = s_scale[h4];
            acc.x *= scl; acc.y *= scl; acc.z *= scl; acc.w *= scl;
        }
        for (int j = 0; j < m_e; j++) {
            const float4* row = (const float4*)(g_xl1 + (size_t)s_src[j] * F1);
            float4 v = row[t];
            float wg = s_lg[j][h4];
            acc.x = fmaf(wg, v.x, acc.x);
            acc.y = fmaf(wg, v.y, acc.y);
            acc.z = fmaf(wg, v.z, acc.z);
            acc.w = fmaf(wg, v.w, acc.w);
        }
        __syncthreads();                       // protect s_lg/s_src reuse
    }

    // epilogue: normalize, bias, relu; fused layer-2 projections + block reduce
    float invd = 1.0f / s_den[h4];
    int f0 = 4 * t;
    float r0 = fmaxf(fmaf(acc.x, invd, bias1[f0 + 0]), 0.0f);
    float r1 = fmaxf(fmaf(acc.y, invd, bias1[f0 + 1]), 0.0f);
    float r2 = fmaxf(fmaf(acc.z, invd, bias1[f0 + 2]), 0.0f);
    float r3 = fmaxf(fmaf(acc.w, invd, bias1[f0 + 3]), 0.0f);
    float pl = fmaf(r0, Wl2[f0], fmaf(r1, Wl2[f0 + 1],
               fmaf(r2, Wl2[f0 + 2], r3 * Wl2[f0 + 3])));
    float pr = fmaf(r0, Wr2[f0], fmaf(r1, Wr2[f0 + 1],
               fmaf(r2, Wr2[f0 + 2], r3 * Wr2[f0 + 3])));
#pragma unroll
    for (int off = 16; off > 0; off >>= 1) {
        pl += __shfl_down_sync(0xffffffffu, pl, off);
        pr += __shfl_down_sync(0xffffffffu, pr, off);
    }
    if (lane == 0) { s_r1[w] = pl; s_r2[w] = pr; }
    __syncthreads();
    if (t == 0) {
        g_xl2[i] = s_r1[0] + s_r1[1] + s_r1[2] + s_r1[3] + bl2[0];
        g_xr2[i] = s_r2[0] + s_r2[1] + s_r2[2] + s_r2[3] + br2[0];
    }
}

// ---------------- K5: fused layer-2 (warp = dst node) --------------------------
// src read coalesced from g_esrc; logits stored at CSR position j (coalesced).
__global__ void k_l2(const float* __restrict__ att2,
                     const float* __restrict__ bias2,
                     float* __restrict__ out) {
    int gw = (blockIdx.x * blockDim.x + threadIdx.x) >> 5;
    if (gw >= NN) return;
    int lane = threadIdx.x & 31;
    int i = gw;
    int start = g_rowptr[i], end = g_rowptr[i + 1];
    float a2 = att2[0];
    float xr = g_xr2[i];

    // pass 1: logits + warp max
    float m = -INFINITY;
    for (int j = start + lane; j < end; j += 32) {
        float l = lrelu(g_xl2[g_esrc[j]] + xr) * a2;
        g_l2[j] = l;
        m = fmaxf(m, l);
    }
#pragma unroll
    for (int off = 16; off > 0; off >>= 1)
        m = fmaxf(m, __shfl_xor_sync(0xffffffffu, m, off));

    // pass 2: denominator (coalesced)
    float den = 0.0f;
    for (int j = start + lane; j < end; j += 32)
        den += __expf(g_l2[j] - m);
#pragma unroll
    for (int off = 16; off > 0; off >>= 1)
        den += __shfl_xor_sync(0xffffffffu, den, off);
    float invden = 1.0f / den;

    // pass 3: alpha out + weighted sum
    float acc = 0.0f;
    for (int j = start + lane; j < end; j += 32) {
        int e = g_eperm[j];
        float alpha = __expf(g_l2[j] - m) * invden;
        out[NN + e] = alpha;
        acc = fmaf(alpha, g_xl2[g_esrc[j]], acc);
    }
#pragma unroll
    for (int off = 16; off > 0; off >>= 1)
        acc += __shfl_xor_sync(0xffffffffu, acc, off);
    if (lane == 0) out[i] = acc + bias2[0];
}

// ---------------- launch ----------------
extern "C" void kernel_launch(void* const* d_in, const int* in_sizes, int n_in,
                              void* d_out, int out_size) {
    const float* x     = (const float*)d_in[0];
    const int*   ei    = (const int*)d_in[1];
    const float* Wl1   = (const float*)d_in[2];
    const float* bl1   = (const float*)d_in[3];
    const float* Wr1   = (const float*)d_in[4];
    const float* br1   = (const float*)d_in[5];
    const float* att1  = (const float*)d_in[6];
    const float* bias1 = (const float*)d_in[7];
    const float* Wl2   = (const float*)d_in[8];
    const float* bl2   = (const float*)d_in[9];
    const float* Wr2   = (const float*)d_in[10];
    const float* br2   = (const float*)d_in[11];
    const float* att2  = (const float*)d_in[12];
    const float* bias2 = (const float*)d_in[13];
    float* out = (float*)d_out;

    k_init0 <<<(NN + 255) / 256, 256>>>();
    k_degree<<<(EE + 255) / 256, 256>>>(ei);
    k_scan  <<<1, 1024>>>();
    k_scatter<<<(EE + 255) / 256, 256>>>(ei);
    k_lin1  <<<(NN + GN - 1) / GN, 512>>>(x, Wl1, bl1, Wr1, br1);
    k_fused1<<<NN, BT>>>(att1, bias1, Wl2, bl2, Wr2, br2);
    k_l2    <<<(NN * 32 + 255) / 256, 256>>>(att2, bias2, out);
}

// round 16
// speedup vs baseline: 1.9166x; 1.0705x over previous
#include <cuda_runtime.h>
#include <cuda_fp16.h>
#include <math.h>

#define NN 50000
#define EO 400000
#define EE 450000
#define F1 512
#define H1 8

// ---------------- scratch (device globals; no runtime allocation) ----------------
__device__ __align__(16) __half g_xl1h[(size_t)NN * F1]; // 51.2 MB (L2-resident)
__device__ __align__(16) float  g_xr1[(size_t)NN * F1];  // 102.4 MB (streamed once)
__device__ int   g_deg[NN];
__device__ int   g_rowptr[NN + 1];
__device__ int   g_cursor[NN];
__device__ int   g_eperm[EE];      // edge id in CSR(dst) order
__device__ int   g_esrc[EE];       // src node in CSR(dst) order
__device__ float g_xl2[NN];
__device__ float g_xr2[NN];
__device__ float g_l2[EE];

__device__ __forceinline__ int dstof(const int* ei, int e) {
    return (e < EO) ? ei[EO + e] : (e - EO);
}
__device__ __forceinline__ float lrelu(float v) { return v > 0.0f ? v : 0.2f * v; }

// ---------------- K_init: zero degree histogram ----------------
__global__ void k_init0() {
    int t = blockIdx.x * blockDim.x + threadIdx.x;
    if (t < NN) g_deg[t] = 0;
}

// ---------------- K0: degree histogram ----------------
__global__ void k_degree(const int* __restrict__ ei) {
    int e = blockIdx.x * blockDim.x + threadIdx.x;
    if (e >= EE) return;
    atomicAdd(&g_deg[dstof(ei, e)], 1);
}

// ---------------- K1: thread-coarsened exclusive scan (rowptr + cursor) --------
__global__ void k_scan() {
    __shared__ int sh[1024];
    const int PER = (NN + 1023) / 1024;   // 49
    int t = threadIdx.x;
    int base = t * PER;
    int lim = (base < NN) ? min(PER, NN - base) : 0;
    int sum = 0;
    for (int k = 0; k < lim; k++) sum += g_deg[base + k];
    sh[t] = sum;
    __syncthreads();
    for (int off = 1; off < 1024; off <<= 1) {
        int add = (t >= off) ? sh[t - off] : 0;
        __syncthreads();
        sh[t] += add;
        __syncthreads();
    }
    int run = sh[t] - sum;                 // exclusive prefix of this segment
    for (int k = 0; k < lim; k++) {
        int v = g_deg[base + k];
        g_cursor[base + k] = run;
        run += v;
        g_rowptr[base + k + 1] = run;
    }
    if (t == 0) g_rowptr[0] = 0;
}

// ---------------- K2: scatter edge ids + src into CSR (dst-grouped) ----------
__global__ void k_scatter(const int* __restrict__ ei) {
    int e = blockIdx.x * blockDim.x + threadIdx.x;
    if (e >= EE) return;
    int s, d;
    if (e < EO) { s = ei[e]; d = ei[EO + e]; }
    else        { s = e - EO; d = s; }
    int pos = atomicAdd(&g_cursor[d], 1);
    g_eperm[pos] = e;
    g_esrc[pos]  = s;
}

// ---------------- K3: layer-1 linear transforms (64 nodes/block, W in regs) ----
// xl -> fp16 table (gathered later), xr -> fp32 (streamed once).
#define GN 64
__global__ void __launch_bounds__(512) k_lin1(
    const float* __restrict__ x,
    const float* __restrict__ Wl, const float* __restrict__ bl,
    const float* __restrict__ Wr, const float* __restrict__ br) {
    __shared__ float xs[GN][24];
    int t = threadIdx.x;
    int n0 = blockIdx.x * GN;
    for (int idx = t; idx < GN * 23; idx += 512) {
        int n = idx / 23, k = idx % 23;
        int gi = n0 + n;
        xs[n][k] = (gi < NN) ? x[gi * 23 + k] : 0.0f;
    }
    float wl[23], wr[23];
#pragma unroll
    for (int k = 0; k < 23; k++) { wl[k] = Wl[k * F1 + t]; wr[k] = Wr[k * F1 + t]; }
    float bll = bl[t], brr = br[t];
    __syncthreads();
    for (int n = 0; n < GN; n++) {
        int gi = n0 + n;
        if (gi >= NN) break;
        float al = bll, ar = brr;
#pragma unroll
        for (int k = 0; k < 23; k++) {
            float xv = xs[n][k];
            al = fmaf(xv, wl[k], al);
            ar = fmaf(xv, wr[k], ar);
        }
        g_xl1h[(size_t)gi * F1 + t] = __float2half(al);
        g_xr1[(size_t)gi * F1 + t]  = ar;
    }
}

// ---------------- K4: fused layer-1 attention (block = dst node, 128 thr) ------
// fp16 row gather (1 KB/row). Phase 1: warp per edge, 2 edges in flight,
// 8-lane segmented head reduction. Phase 2: warp w -> heads {w, w+4}, online
// softmax. Phase 3: coalesced uint2 (4 halves) aggregation, fp32 accum.
// Epilogue: bias+relu, fused layer-2 input projections -> g_xl2/g_xr2.
#define BT 128
#define CHF 32
__global__ void __launch_bounds__(BT) k_fused1(
    const float* __restrict__ att,
    const float* __restrict__ bias1,
    const float* __restrict__ Wl2, const float* __restrict__ bl2,
    const float* __restrict__ Wr2, const float* __restrict__ br2) {
    __shared__ __align__(16) float s_xr[F1];   // 2 KB
    __shared__ __align__(16) float s_att[F1];  // 2 KB
    __shared__ float s_lg[CHF][9];             // logits -> weights (padded)
    __shared__ int   s_src[CHF];
    __shared__ float s_m[H1], s_den[H1], s_scale[H1];
    __shared__ float s_r1[4], s_r2[4];

    int i = blockIdx.x;
    int t = threadIdx.x;
    int w = t >> 5, lane = t & 31;
    int start = g_rowptr[i], end = g_rowptr[i + 1];

    {   // load xr row (streaming: read-once) + att
        const float4* xr4 = (const float4*)(g_xr1 + (size_t)i * F1);
        ((float4*)s_xr)[t] = __ldcs(&xr4[t]);
        s_att[t]       = att[t];
        s_att[t + 128] = att[t + 128];
        s_att[t + 256] = att[t + 256];
        s_att[t + 384] = att[t + 384];
    }
    if (t < H1) { s_m[t] = -INFINITY; s_den[t] = 0.0f; }
    __syncthreads();

    int h4 = t >> 4;                           // head of this thread's 4-feature slot
    float4 acc = make_float4(0.f, 0.f, 0.f, 0.f);

    for (int c = start; c < end; c += CHF) {
        int m_e = min(CHF, end - c);

        // ---- phase 1: logits, warp per edge, 2 edges concurrently ----
        for (int leA = w; leA < m_e; leA += 8) {
            int leB = leA + 4;
            bool hasB = leB < m_e;
            int sA = g_esrc[c + leA];
            int sB = hasB ? g_esrc[c + leB] : sA;
            if (lane == 0) { s_src[leA] = sA; if (hasB) s_src[leB] = sB; }
            const uint4* prA = (const uint4*)(g_xl1h + (size_t)sA * F1);
            const uint4* prB = (const uint4*)(g_xl1h + (size_t)sB * F1);
            float pA[2], pB[2];
#pragma unroll
            for (int k = 0; k < 2; k++) {
                int fi = k * 32 + lane;                  // uint4 idx: 8 halves
                uint4 vA = prA[fi];
                uint4 vB = prB[fi];
                float4 xa = ((const float4*)s_xr)[2 * fi];
                float4 xb = ((const float4*)s_xr)[2 * fi + 1];
                float4 aa = ((const float4*)s_att)[2 * fi];
                float4 ab = ((const float4*)s_att)[2 * fi + 1];
                {
                    float2 f0 = __half22float2(*(const __half2*)&vA.x);
                    float2 f1 = __half22float2(*(const __half2*)&vA.y);
                    float2 f2 = __half22float2(*(const __half2*)&vA.z);
                    float2 f3 = __half22float2(*(const __half2*)&vA.w);
                    pA[k] = fmaf(lrelu(f0.x + xa.x), aa.x,
                            fmaf(lrelu(f0.y + xa.y), aa.y,
                            fmaf(lrelu(f1.x + xa.z), aa.z,
                            fmaf(lrelu(f1.y + xa.w), aa.w,
                            fmaf(lrelu(f2.x + xb.x), ab.x,
                            fmaf(lrelu(f2.y + xb.y), ab.y,
                            fmaf(lrelu(f3.x + xb.z), ab.z,
                                 lrelu(f3.y + xb.w) * ab.w)))))));
                }
                {
                    float2 f0 = __half22float2(*(const __half2*)&vB.x);
                    float2 f1 = __half22float2(*(const __half2*)&vB.y);
                    float2 f2 = __half22float2(*(const __half2*)&vB.z);
                    float2 f3 = __half22float2(*(const __half2*)&vB.w);
                    pB[k] = fmaf(lrelu(f0.x + xa.x), aa.x,
                            fmaf(lrelu(f0.y + xa.y), aa.y,
                            fmaf(lrelu(f1.x + xa.z), aa.z,
                            fmaf(lrelu(f1.y + xa.w), aa.w,
                            fmaf(lrelu(f2.x + xb.x), ab.x,
                            fmaf(lrelu(f2.y + xb.y), ab.y,
                            fmaf(lrelu(f3.x + xb.z), ab.z,
                                 lrelu(f3.y + xb.w) * ab.w)))))));
                }
            }
            // 8-lane segments: k=0 -> head lane>>3, k=1 -> head 4+(lane>>3)
#pragma unroll
            for (int off = 1; off < 8; off <<= 1) {
                pA[0] += __shfl_xor_sync(0xffffffffu, pA[0], off);
                pA[1] += __shfl_xor_sync(0xffffffffu, pA[1], off);
                pB[0] += __shfl_xor_sync(0xffffffffu, pB[0], off);
                pB[1] += __shfl_xor_sync(0xffffffffu, pB[1], off);
            }
            if ((lane & 7) == 0) {
                int hseg = lane >> 3;
                s_lg[leA][hseg]     = pA[0];
                s_lg[leA][hseg + 4] = pA[1];
                if (hasB) {
                    s_lg[leB][hseg]     = pB[0];
                    s_lg[leB][hseg + 4] = pB[1];
                }
            }
        }
        __syncthreads();

        // ---- phase 2: online softmax, warp w handles heads w and w+4 ----
        for (int hh = w; hh < H1; hh += 4) {
            float cm = -INFINITY;
            for (int j = lane; j < m_e; j += 32) cm = fmaxf(cm, s_lg[j][hh]);
#pragma unroll
            for (int off = 16; off > 0; off >>= 1)
                cm = fmaxf(cm, __shfl_xor_sync(0xffffffffu, cm, off));
            float m_old = s_m[hh];
            cm = fmaxf(cm, m_old);
            float dn = 0.0f;
            for (int j = lane; j < m_e; j += 32) {
                float wj = __expf(s_lg[j][hh] - cm);
                s_lg[j][hh] = wj;
                dn += wj;
            }
#pragma unroll
            for (int off = 16; off > 0; off >>= 1)
                dn += __shfl_xor_sync(0xffffffffu, dn, off);
            if (lane == 0) {
                float sc = __expf(m_old - cm);  // first chunk: exp(-inf)=0
                s_scale[hh] = sc;
                s_den[hh] = s_den[hh] * sc + dn;
                s_m[hh] = cm;
            }
        }
        __syncthreads();

        // ---- phase 3: coalesced fp16 aggregation (rows L1/L2-hot) ----
        {
            float scl = s_scale[h4];
            acc.x *= scl; acc.y *= scl; acc.z *= scl; acc.w *= scl;
        }
        for (int j = 0; j < m_e; j++) {
            const uint2* row = (const uint2*)(g_xl1h + (size_t)s_src[j] * F1);
            uint2 d = row[t];                       // 4 halves = features 4t..4t+3
            float2 f0 = __half22float2(*(const __half2*)&d.x);
            float2 f1 = __half22float2(*(const __half2*)&d.y);
            float wg = s_lg[j][h4];
            acc.x = fmaf(wg, f0.x, acc.x);
            acc.y = fmaf(wg, f0.y, acc.y);
            acc.z = fmaf(wg, f1.x, acc.z);
            acc.w = fmaf(wg, f1.y, acc.w);
        }
        __syncthreads();                       // protect s_lg/s_src reuse
    }

    // epilogue: normalize, bias, relu; fused layer-2 projections + block reduce
    float invd = 1.0f / s_den[h4];
    int f0i = 4 * t;
    float r0 = fmaxf(fmaf(acc.x, invd, bias1[f0i + 0]), 0.0f);
    float r1 = fmaxf(fmaf(acc.y, invd, bias1[f0i + 1]), 0.0f);
    float r2 = fmaxf(fmaf(acc.z, invd, bias1[f0i + 2]), 0.0f);
    float r3 = fmaxf(fmaf(acc.w, invd, bias1[f0i + 3]), 0.0f);
    float pl = fmaf(r0, Wl2[f0i], fmaf(r1, Wl2[f0i + 1],
               fmaf(r2, Wl2[f0i + 2], r3 * Wl2[f0i + 3])));
    float pr = fmaf(r0, Wr2[f0i], fmaf(r1, Wr2[f0i + 1],
               fmaf(r2, Wr2[f0i + 2], r3 * Wr2[f0i + 3])));
#pragma unroll
    for (int off = 16; off > 0; off >>= 1) {
        pl += __shfl_down_sync(0xffffffffu, pl, off);
        pr += __shfl_down_sync(0xffffffffu, pr, off);
    }
    if (lane == 0) { s_r1[w] = pl; s_r2[w] = pr; }
    __syncthreads();
    if (t == 0) {
        g_xl2[i] = s_r1[0] + s_r1[1] + s_r1[2] + s_r1[3] + bl2[0];
        g_xr2[i] = s_r2[0] + s_r2[1] + s_r2[2] + s_r2[3] + br2[0];
    }
}

// ---------------- K5: fused layer-2 (warp = dst node) --------------------------
// src read coalesced from g_esrc; logits stored at CSR position j (coalesced).
__global__ void k_l2(const float* __restrict__ att2,
                     const float* __restrict__ bias2,
                     float* __restrict__ out) {
    int gw = (blockIdx.x * blockDim.x + threadIdx.x) >> 5;
    if (gw >= NN) return;
    int lane = threadIdx.x & 31;
    int i = gw;
    int start = g_rowptr[i], end = g_rowptr[i + 1];
    float a2 = att2[0];
    float xr = g_xr2[i];

    // pass 1: logits + warp max
    float m = -INFINITY;
    for (int j = start + lane; j < end; j += 32) {
        float l = lrelu(g_xl2[g_esrc[j]] + xr) * a2;
        g_l2[j] = l;
        m = fmaxf(m, l);
    }
#pragma unroll
    for (int off = 16; off > 0; off >>= 1)
        m = fmaxf(m, __shfl_xor_sync(0xffffffffu, m, off));

    // pass 2: denominator (coalesced)
    float den = 0.0f;
    for (int j = start + lane; j < end; j += 32)
        den += __expf(g_l2[j] - m);
#pragma unroll
    for (int off = 16; off > 0; off >>= 1)
        den += __shfl_xor_sync(0xffffffffu, den, off);
    float invden = 1.0f / den;

    // pass 3: alpha out + weighted sum
    float acc = 0.0f;
    for (int j = start + lane; j < end; j += 32) {
        int e = g_eperm[j];
        float alpha = __expf(g_l2[j] - m) * invden;
        out[NN + e] = alpha;
        acc = fmaf(alpha, g_xl2[g_esrc[j]], acc);
    }
#pragma unroll
    for (int off = 16; off > 0; off >>= 1)
        acc += __shfl_xor_sync(0xffffffffu, acc, off);
    if (lane == 0) out[i] = acc + bias2[0];
}

// ---------------- launch ----------------
extern "C" void kernel_launch(void* const* d_in, const int* in_sizes, int n_in,
                              void* d_out, int out_size) {
    const float* x     = (const float*)d_in[0];
    const int*   ei    = (const int*)d_in[1];
    const float* Wl1   = (const float*)d_in[2];
    const float* bl1   = (const float*)d_in[3];
    const float* Wr1   = (const float*)d_in[4];
    const float* br1   = (const float*)d_in[5];
    const float* att1  = (const float*)d_in[6];
    const float* bias1 = (const float*)d_in[7];
    const float* Wl2   = (const float*)d_in[8];
    const float* bl2   = (const float*)d_in[9];
    const float* Wr2   = (const float*)d_in[10];
    const float* br2   = (const float*)d_in[11];
    const float* att2  = (const float*)d_in[12];
    const float* bias2 = (const float*)d_in[13];
    float* out = (float*)d_out;

    k_init0 <<<(NN + 255) / 256, 256>>>();
    k_degree<<<(EE + 255) / 256, 256>>>(ei);
    k_scan  <<<1, 1024>>>();
    k_scatter<<<(EE + 255) / 256, 256>>>(ei);
    k_lin1  <<<(NN + GN - 1) / GN, 512>>>(x, Wl1, bl1, Wr1, br1);
    k_fused1<<<NN, BT>>>(att1, bias1, Wl2, bl2, Wr2, br2);
    k_l2    <<<(NN * 32 + 255) / 256, 256>>>(att2, bias2, out);
}

// round 17
// speedup vs baseline: 2.3281x; 1.2147x over previous
#include <cuda_runtime.h>
#include <cuda_fp16.h>
#include <math.h>

#define NN 50000
#define EO 400000
#define EE 450000
#define F1 512
#define H1 8

// ---------------- scratch (device globals; no runtime allocation) ----------------
__device__ __align__(16) __half g_xl1h[(size_t)NN * F1]; // 51.2 MB (L2-resident)
__device__ __align__(16) float  g_xr1[(size_t)NN * F1];  // 102.4 MB (streamed once)
__device__ int   g_deg[NN];
__device__ int   g_rowptr[NN + 1];
__device__ int   g_cursor[NN];
__device__ int   g_eperm[EE];      // edge id in CSR(dst) order
__device__ int   g_esrc[EE];       // src node in CSR(dst) order
__device__ float g_xl2[NN];
__device__ float g_xr2[NN];
__device__ float g_l2[EE];

__device__ __forceinline__ int dstof(const int* ei, int e) {
    return (e < EO) ? ei[EO + e] : (e - EO);
}
__device__ __forceinline__ float lrelu(float v) { return v > 0.0f ? v : 0.2f * v; }

// ---------------- K_init: zero degree histogram ----------------
__global__ void k_init0() {
    int t = blockIdx.x * blockDim.x + threadIdx.x;
    if (t < NN) g_deg[t] = 0;
}

// ---------------- K0: degree histogram ----------------
__global__ void k_degree(const int* __restrict__ ei) {
    int e = blockIdx.x * blockDim.x + threadIdx.x;
    if (e >= EE) return;
    atomicAdd(&g_deg[dstof(ei, e)], 1);
}

// ---------------- K1: thread-coarsened exclusive scan (rowptr + cursor) --------
__global__ void k_scan() {
    __shared__ int sh[1024];
    const int PER = (NN + 1023) / 1024;   // 49
    int t = threadIdx.x;
    int base = t * PER;
    int lim = (base < NN) ? min(PER, NN - base) : 0;
    int sum = 0;
    for (int k = 0; k < lim; k++) sum += g_deg[base + k];
    sh[t] = sum;
    __syncthreads();
    for (int off = 1; off < 1024; off <<= 1) {
        int add = (t >= off) ? sh[t - off] : 0;
        __syncthreads();
        sh[t] += add;
        __syncthreads();
    }
    int run = sh[t] - sum;                 // exclusive prefix of this segment
    for (int k = 0; k < lim; k++) {
        int v = g_deg[base + k];
        g_cursor[base + k] = run;
        run += v;
        g_rowptr[base + k + 1] = run;
    }
    if (t == 0) g_rowptr[0] = 0;
}

// ---------------- K2: scatter edge ids + src into CSR (dst-grouped) ----------
__global__ void k_scatter(const int* __restrict__ ei) {
    int e = blockIdx.x * blockDim.x + threadIdx.x;
    if (e >= EE) return;
    int s, d;
    if (e < EO) { s = ei[e]; d = ei[EO + e]; }
    else        { s = e - EO; d = s; }
    int pos = atomicAdd(&g_cursor[d], 1);
    g_eperm[pos] = e;
    g_esrc[pos]  = s;
}

// ---------------- K3: layer-1 linear transforms (64 nodes/block, W in regs) ----
// xl -> fp16 table (gathered later), xr -> fp32 (streamed once).
#define GN 64
__global__ void __launch_bounds__(512) k_lin1(
    const float* __restrict__ x,
    const float* __restrict__ Wl, const float* __restrict__ bl,
    const float* __restrict__ Wr, const float* __restrict__ br) {
    __shared__ float xs[GN][24];
    int t = threadIdx.x;
    int n0 = blockIdx.x * GN;
    for (int idx = t; idx < GN * 23; idx += 512) {
        int n = idx / 23, k = idx % 23;
        int gi = n0 + n;
        xs[n][k] = (gi < NN) ? x[gi * 23 + k] : 0.0f;
    }
    float wl[23], wr[23];
#pragma unroll
    for (int k = 0; k < 23; k++) { wl[k] = Wl[k * F1 + t]; wr[k] = Wr[k * F1 + t]; }
    float bll = bl[t], brr = br[t];
    __syncthreads();
    for (int n = 0; n < GN; n++) {
        int gi = n0 + n;
        if (gi >= NN) break;
        float al = bll, ar = brr;
#pragma unroll
        for (int k = 0; k < 23; k++) {
            float xv = xs[n][k];
            al = fmaf(xv, wl[k], al);
            ar = fmaf(xv, wr[k], ar);
        }
        g_xl1h[(size_t)gi * F1 + t] = __float2half(al);
        g_xr1[(size_t)gi * F1 + t]  = ar;
    }
}

// ---------------- K4: fused layer-1 attention (WARP = dst node) ----------------
// 4 warps/block, each owning a node end-to-end: no block barriers in the loop.
// Phase 1: warp-per-edge logits, 2 edges in flight, 8-lane head segments.
// Phase 2: lanes 0-7 warp-local online softmax (head = lane).
// Phase 3: lane owns features [16*lane,16*lane+16) (head lane>>2), 2xLDG.128/edge.
// Epilogue: bias+relu + fused layer-2 projections, pure warp reduction.
#define BT 128
#define NW 4
#define CHW 32
__global__ void __launch_bounds__(BT) k_fused1(
    const float* __restrict__ att,
    const float* __restrict__ bias1,
    const float* __restrict__ Wl2, const float* __restrict__ bl2,
    const float* __restrict__ Wr2, const float* __restrict__ br2) {
    __shared__ __align__(16) float s_att[F1];        // 2 KB, block-shared
    __shared__ __align__(16) float s_xr[NW][F1];     // 8 KB, per-warp
    __shared__ float s_lg[NW][CHW][9];               // 4.6 KB logits->weights
    __shared__ int   s_src[NW][CHW];
    __shared__ float s_m[NW][H1], s_den[NW][H1], s_scale[NW][H1];

    int t = threadIdx.x;
    int w = t >> 5, lane = t & 31;
    int node = blockIdx.x * NW + w;

    s_att[t]       = att[t];
    s_att[t + 128] = att[t + 128];
    s_att[t + 256] = att[t + 256];
    s_att[t + 384] = att[t + 384];
    __syncthreads();
    if (node >= NN) return;

    int start = g_rowptr[node], end = g_rowptr[node + 1];

    {   // per-warp xr row load (streamed, read-once): 4 float4 per lane
        const float4* xr4 = (const float4*)(g_xr1 + (size_t)node * F1);
#pragma unroll
        for (int k = 0; k < 4; k++)
            ((float4*)s_xr[w])[k * 32 + lane] = __ldcs(&xr4[k * 32 + lane]);
    }
    if (lane < H1) { s_m[w][lane] = -INFINITY; s_den[w][lane] = 0.0f; }
    __syncwarp();

    int hl = lane >> 2;                 // head of this lane's 16-feature slice
    float4 acc[4];
#pragma unroll
    for (int k = 0; k < 4; k++) acc[k] = make_float4(0.f, 0.f, 0.f, 0.f);

    for (int c = start; c < end; c += CHW) {
        int m_e = min(CHW, end - c);

        // ---- phase 1: logits, 2 edges concurrently ----
        for (int leA = 0; leA < m_e; leA += 2) {
            int leB = leA + 1;
            bool hasB = leB < m_e;
            int sA = g_esrc[c + leA];
            int sB = hasB ? g_esrc[c + leB] : sA;
            if (lane == 0) { s_src[w][leA] = sA; if (hasB) s_src[w][leB] = sB; }
            const uint4* prA = (const uint4*)(g_xl1h + (size_t)sA * F1);
            const uint4* prB = (const uint4*)(g_xl1h + (size_t)sB * F1);
            float pA[2], pB[2];
#pragma unroll
            for (int k = 0; k < 2; k++) {
                int fi = k * 32 + lane;              // uint4 idx: 8 halves
                uint4 vA = prA[fi];
                uint4 vB = prB[fi];
                float4 xa = ((const float4*)s_xr[w])[2 * fi];
                float4 xb = ((const float4*)s_xr[w])[2 * fi + 1];
                float4 aa = ((const float4*)s_att)[2 * fi];
                float4 ab = ((const float4*)s_att)[2 * fi + 1];
                {
                    float2 f0 = __half22float2(*(const __half2*)&vA.x);
                    float2 f1 = __half22float2(*(const __half2*)&vA.y);
                    float2 f2 = __half22float2(*(const __half2*)&vA.z);
                    float2 f3 = __half22float2(*(const __half2*)&vA.w);
                    pA[k] = fmaf(lrelu(f0.x + xa.x), aa.x,
                            fmaf(lrelu(f0.y + xa.y), aa.y,
                            fmaf(lrelu(f1.x + xa.z), aa.z,
                            fmaf(lrelu(f1.y + xa.w), aa.w,
                            fmaf(lrelu(f2.x + xb.x), ab.x,
                            fmaf(lrelu(f2.y + xb.y), ab.y,
                            fmaf(lrelu(f3.x + xb.z), ab.z,
                                 lrelu(f3.y + xb.w) * ab.w)))))));
                }
                {
                    float2 f0 = __half22float2(*(const __half2*)&vB.x);
                    float2 f1 = __half22float2(*(const __half2*)&vB.y);
                    float2 f2 = __half22float2(*(const __half2*)&vB.z);
                    float2 f3 = __half22float2(*(const __half2*)&vB.w);
                    pB[k] = fmaf(lrelu(f0.x + xa.x), aa.x,
                            fmaf(lrelu(f0.y + xa.y), aa.y,
                            fmaf(lrelu(f1.x + xa.z), aa.z,
                            fmaf(lrelu(f1.y + xa.w), aa.w,
                            fmaf(lrelu(f2.x + xb.x), ab.x,
                            fmaf(lrelu(f2.y + xb.y), ab.y,
                            fmaf(lrelu(f3.x + xb.z), ab.z,
                                 lrelu(f3.y + xb.w) * ab.w)))))));
                }
            }
            // 8-lane segments: k=0 -> head lane>>3, k=1 -> head 4+(lane>>3)
#pragma unroll
            for (int off = 1; off < 8; off <<= 1) {
                pA[0] += __shfl_xor_sync(0xffffffffu, pA[0], off);
                pA[1] += __shfl_xor_sync(0xffffffffu, pA[1], off);
                pB[0] += __shfl_xor_sync(0xffffffffu, pB[0], off);
                pB[1] += __shfl_xor_sync(0xffffffffu, pB[1], off);
            }
            if ((lane & 7) == 0) {
                int hseg = lane >> 3;
                s_lg[w][leA][hseg]     = pA[0];
                s_lg[w][leA][hseg + 4] = pA[1];
                if (hasB) {
                    s_lg[w][leB][hseg]     = pB[0];
                    s_lg[w][leB][hseg + 4] = pB[1];
                }
            }
        }
        __syncwarp();

        // ---- phase 2: warp-local online softmax, lanes 0-7 (head = lane) ----
        if (lane < H1) {
            float cm = -INFINITY;
            for (int j = 0; j < m_e; j++) cm = fmaxf(cm, s_lg[w][j][lane]);
            float m_old = s_m[w][lane];
            cm = fmaxf(cm, m_old);
            float dn = 0.0f;
            for (int j = 0; j < m_e; j++) {
                float wj = __expf(s_lg[w][j][lane] - cm);
                s_lg[w][j][lane] = wj;
                dn += wj;
            }
            float sc = __expf(m_old - cm);      // first chunk: exp(-inf)=0
            s_scale[w][lane] = sc;
            s_den[w][lane] = s_den[w][lane] * sc + dn;
            s_m[w][lane] = cm;
        }
        __syncwarp();

        // ---- phase 3: aggregation, lane = 16 features of single head ----
        {
            float scl = s_scale[w][hl];
#pragma unroll
            for (int k = 0; k < 4; k++) {
                acc[k].x *= scl; acc[k].y *= scl; acc[k].z *= scl; acc[k].w *= scl;
            }
        }
        for (int j = 0; j < m_e; j++) {
            const uint4* row = (const uint4*)(g_xl1h + (size_t)s_src[w][j] * F1);
            uint4 d0 = row[2 * lane];
            uint4 d1 = row[2 * lane + 1];
            float wg = s_lg[w][j][hl];
            float2 f;
            f = __half22float2(*(const __half2*)&d0.x); acc[0].x = fmaf(wg, f.x, acc[0].x); acc[0].y = fmaf(wg, f.y, acc[0].y);
            f = __half22float2(*(const __half2*)&d0.y); acc[0].z = fmaf(wg, f.x, acc[0].z); acc[0].w = fmaf(wg, f.y, acc[0].w);
            f = __half22float2(*(const __half2*)&d0.z); acc[1].x = fmaf(wg, f.x, acc[1].x); acc[1].y = fmaf(wg, f.y, acc[1].y);
            f = __half22float2(*(const __half2*)&d0.w); acc[1].z = fmaf(wg, f.x, acc[1].z); acc[1].w = fmaf(wg, f.y, acc[1].w);
            f = __half22float2(*(const __half2*)&d1.x); acc[2].x = fmaf(wg, f.x, acc[2].x); acc[2].y = fmaf(wg, f.y, acc[2].y);
            f = __half22float2(*(const __half2*)&d1.y); acc[2].z = fmaf(wg, f.x, acc[2].z); acc[2].w = fmaf(wg, f.y, acc[2].w);
            f = __half22float2(*(const __half2*)&d1.z); acc[3].x = fmaf(wg, f.x, acc[3].x); acc[3].y = fmaf(wg, f.y, acc[3].y);
            f = __half22float2(*(const __half2*)&d1.w); acc[3].z = fmaf(wg, f.x, acc[3].z); acc[3].w = fmaf(wg, f.y, acc[3].w);
        }
        __syncwarp();                           // protect s_lg/s_src reuse
    }

    // epilogue: normalize, bias, relu; fused layer-2 projections + warp reduce
    float invd = 1.0f / s_den[w][hl];
    int f0 = 16 * lane;
    float pl = 0.0f, pr = 0.0f;
#pragma unroll
    for (int k = 0; k < 4; k++) {
        float4 b4  = *(const float4*)(bias1 + f0 + 4 * k);
        float4 wl4 = *(const float4*)(Wl2  + f0 + 4 * k);
        float4 wr4 = *(const float4*)(Wr2  + f0 + 4 * k);
        float r0 = fmaxf(fmaf(acc[k].x, invd, b4.x), 0.0f);
        float r1 = fmaxf(fmaf(acc[k].y, invd, b4.y), 0.0f);
        float r2 = fmaxf(fmaf(acc[k].z, invd, b4.z), 0.0f);
        float r3 = fmaxf(fmaf(acc[k].w, invd, b4.w), 0.0f);
        pl = fmaf(r0, wl4.x, fmaf(r1, wl4.y, fmaf(r2, wl4.z, fmaf(r3, wl4.w, pl))));
        pr = fmaf(r0, wr4.x, fmaf(r1, wr4.y, fmaf(r2, wr4.z, fmaf(r3, wr4.w, pr))));
    }
#pragma unroll
    for (int off = 16; off > 0; off >>= 1) {
        pl += __shfl_xor_sync(0xffffffffu, pl, off);
        pr += __shfl_xor_sync(0xffffffffu, pr, off);
    }
    if (lane == 0) {
        g_xl2[node] = pl + bl2[0];
        g_xr2[node] = pr + br2[0];
    }
}

// ---------------- K5: fused layer-2 (warp = dst node) --------------------------
// src read coalesced from g_esrc; logits stored at CSR position j (coalesced).
__global__ void k_l2(const float* __restrict__ att2,
                     const float* __restrict__ bias2,
                     float* __restrict__ out) {
    int gw = (blockIdx.x * blockDim.x + threadIdx.x) >> 5;
    if (gw >= NN) return;
    int lane = threadIdx.x & 31;
    int i = gw;
    int start = g_rowptr[i], end = g_rowptr[i + 1];
    float a2 = att2[0];
    float xr = g_xr2[i];

    // pass 1: logits + warp max
    float m = -INFINITY;
    for (int j = start + lane; j < end; j += 32) {
        float l = lrelu(g_xl2[g_esrc[j]] + xr) * a2;
        g_l2[j] = l;
        m = fmaxf(m, l);
    }
#pragma unroll
    for (int off = 16; off > 0; off >>= 1)
        m = fmaxf(m, __shfl_xor_sync(0xffffffffu, m, off));

    // pass 2: denominator (coalesced)
    float den = 0.0f;
    for (int j = start + lane; j < end; j += 32)
        den += __expf(g_l2[j] - m);
#pragma unroll
    for (int off = 16; off > 0; off >>= 1)
        den += __shfl_xor_sync(0xffffffffu, den, off);
    float invden = 1.0f / den;

    // pass 3: alpha out + weighted sum
    float acc = 0.0f;
    for (int j = start + lane; j < end; j += 32) {
        int e = g_eperm[j];
        float alpha = __expf(g_l2[j] - m) * invden;
        out[NN + e] = alpha;
        acc = fmaf(alpha, g_xl2[g_esrc[j]], acc);
    }
#pragma unroll
    for (int off = 16; off > 0; off >>= 1)
        acc += __shfl_xor_sync(0xffffffffu, acc, off);
    if (lane == 0) out[i] = acc + bias2[0];
}

// ---------------- launch ----------------
extern "C" void kernel_launch(void* const* d_in, const int* in_sizes, int n_in,
                              void* d_out, int out_size) {
    const float* x     = (const float*)d_in[0];
    const int*   ei    = (const int*)d_in[1];
    const float* Wl1   = (const float*)d_in[2];
    const float* bl1   = (const float*)d_in[3];
    const float* Wr1   = (const float*)d_in[4];
    const float* br1   = (const float*)d_in[5];
    const float* att1  = (const float*)d_in[6];
    const float* bias1 = (const float*)d_in[7];
    const float* Wl2   = (const float*)d_in[8];
    const float* bl2   = (const float*)d_in[9];
    const float* Wr2   = (const float*)d_in[10];
    const float* br2   = (const float*)d_in[11];
    const float* att2  = (const float*)d_in[12];
    const float* bias2 = (const float*)d_in[13];
    float* out = (float*)d_out;

    k_init0 <<<(NN + 255) / 256, 256>>>();
    k_degree<<<(EE + 255) / 256, 256>>>(ei);
    k_scan  <<<1, 1024>>>();
    k_scatter<<<(EE + 255) / 256, 256>>>(ei);
    k_lin1  <<<(NN + GN - 1) / GN, 512>>>(x, Wl1, bl1, Wr1, br1);
    k_fused1<<<(NN + NW - 1) / NW, BT>>>(att1, bias1, Wl2, bl2, Wr2, br2);
    k_l2    <<<(NN * 32 + 255) / 256, 256>>>(att2, bias2, out);
}